// round 15
// baseline (speedup 1.0000x reference)
#include <cuda_runtime.h>
#include <cuda_fp16.h>
#include <cstdint>

#define NN 50000
#define EE 600000
#define HD 128
#define CC 40
#define NEG 0.1f
#define NTILES ((NN + 127) / 128)

// ---------------- scratch (static device globals; no allocation) ----------------
__device__ float g_bufA[(size_t)NN * HD];
__device__ float g_bufB[(size_t)NN * HD];
__device__ float g_agg[(size_t)NN * HD];
__device__ __half g_x16[(size_t)NN * HD];
__device__ __half g_h16[(size_t)NN * HD];
__device__ float g_inv[NN];
__device__ int   g_cnt[NN];
__device__ int   g_rowptr[NN + 1];
__device__ int   g_rawscan[NN];
__device__ int   g_bsum[128];
__device__ int   g_boff[128];
__device__ int   g_fill[NN];
__device__ int   g_col[EE];
// pre-transposed + split-bf16 weights: W^T stored [N][K] row-major (K=128 contiguous)
__device__ unsigned short g_wth[108544];
__device__ unsigned short g_wtl[108544];

#define WOFF_ENCL 0
#define WOFF_ENCR 16384
#define WOFF_L0L  32768
#define WOFF_L0R  49152
#define WOFF_L1L  65536
#define WOFF_L1R  81920
#define WOFF_DECL 98304
#define WOFF_DECR 103424

__device__ __forceinline__ float* dev_buf(int id) {
    return (id == 0) ? g_bufA : g_bufB;
}

// ---------------- merged prep: zero cnt + weight split + x->fp16 ----------------
__global__ void k_prep0(const float* __restrict__ x,
                        const float* __restrict__ eWl, const float* __restrict__ eWr,
                        const float* __restrict__ lWl, const float* __restrict__ lWr,
                        const float* __restrict__ dWl, const float* __restrict__ dWr) {
    int idx = blockIdx.x * blockDim.x + threadIdx.x;
    if (idx < NN) g_cnt[idx] = 0;

    if (idx < 108544) {
        const float* src;
        int N, e, off;
        if (idx < 98304) {
            int m = idx >> 14; e = idx & 16383; N = 128; off = m << 14;
            switch (m) {
                case 0: src = eWl; break;
                case 1: src = eWr; break;
                case 2: src = lWl; break;
                case 3: src = lWr; break;
                case 4: src = lWl + 16384; break;
                default: src = lWr + 16384; break;
            }
        } else {
            int t = idx - 98304;
            int m = t / 5120; e = t % 5120; N = 40;
            off = 98304 + m * 5120;
            src = m ? dWr : dWl;
        }
        int n = e >> 7;
        int k = e & 127;
        float v = src[(size_t)k * N + n];
        unsigned hp;
        asm("cvt.rn.bf16x2.f32 %0, %1, %2;" : "=r"(hp) : "f"(v), "f"(v));
        unsigned hb = hp & 0xffffu;
        float hf = __uint_as_float(hb << 16);
        float lv = v - hf;
        unsigned lp;
        asm("cvt.rn.bf16x2.f32 %0, %1, %2;" : "=r"(lp) : "f"(lv), "f"(lv));
        g_wth[off + e] = (unsigned short)hb;
        g_wtl[off + e] = (unsigned short)(lp & 0xffffu);
    }

    if (idx < NN * HD / 2) {
        float2 v = ((const float2*)x)[idx];
        ((__half2*)g_x16)[idx] = __floats2half2_rn(v.x, v.y);
    }
}

// ---------------- CSR build ----------------
__global__ void k_deg(const int* __restrict__ dst) {
    int e = blockIdx.x * blockDim.x + threadIdx.x;
    if (e < EE) atomicAdd(&g_cnt[dst[e]], 1);
}

// per-block inclusive scan (512/block) -> g_rawscan, block totals -> g_bsum
__global__ void k_scan1() {
    __shared__ int s[512];
    int i = blockIdx.x * 512 + threadIdx.x;
    int v = (i < NN) ? g_cnt[i] : 0;
    s[threadIdx.x] = v;
    __syncthreads();
    for (int off = 1; off < 512; off <<= 1) {
        int t = (threadIdx.x >= (unsigned)off) ? s[threadIdx.x - off] : 0;
        __syncthreads();
        s[threadIdx.x] += t;
        __syncthreads();
    }
    if (i < NN) g_rawscan[i] = s[threadIdx.x];
    if (threadIdx.x == 511) g_bsum[blockIdx.x] = s[511];
}

// exclusive scan of block sums (single 128-thread block)
__global__ void k_scan2() {
    __shared__ int s[128];
    int t = threadIdx.x;
    int nb = (NN + 511) / 512;
    int v = (t < nb) ? g_bsum[t] : 0;
    s[t] = v;
    __syncthreads();
    for (int off = 1; off < 128; off <<= 1) {
        int u = (t >= off) ? s[t - off] : 0;
        __syncthreads();
        s[t] += u;
        __syncthreads();
    }
    if (t < nb) g_boff[t] = (t == 0) ? 0 : s[t - 1];
}

__global__ void k_prep() {
    int i = blockIdx.x * blockDim.x + threadIdx.x;
    if (i < NN) {
        int c = g_cnt[i];
        int end = g_rawscan[i] + g_boff[i >> 9];
        g_rowptr[i + 1] = end;
        g_fill[i] = end - c;
        g_inv[i] = 1.0f / (float)(c > 0 ? c : 1);
        if (i == 0) g_rowptr[0] = 0;
    }
}

__global__ void k_fill(const int* __restrict__ src, const int* __restrict__ dst) {
    int e = blockIdx.x * blockDim.x + threadIdx.x;
    if (e < EE) {
        int pos = atomicAdd(&g_fill[dst[e]], 1);
        g_col[pos] = src[e];
    }
}

// ---------------- mean aggregation: one warp per node, fp16 gather, 2-edge unroll ----------------
__global__ void k_agg(int srcsel) {
    int warp = (blockIdx.x * blockDim.x + threadIdx.x) >> 5;
    if (warp >= NN) return;
    int lane = threadIdx.x & 31;
    const __half* in = srcsel ? g_h16 : g_x16;
    int beg = g_rowptr[warp];
    int end = g_rowptr[warp + 1];
    float4 acc = make_float4(0.f, 0.f, 0.f, 0.f);
    int e = beg;
    for (; e + 1 < end; e += 2) {
        int s0 = g_col[e];
        int s1 = g_col[e + 1];
        uint2 u0 = *(const uint2*)(in + (size_t)s0 * HD + lane * 4);
        uint2 u1 = *(const uint2*)(in + (size_t)s1 * HD + lane * 4);
        float2 a0 = __half22float2(*reinterpret_cast<const __half2*>(&u0.x));
        float2 a1 = __half22float2(*reinterpret_cast<const __half2*>(&u0.y));
        float2 b0 = __half22float2(*reinterpret_cast<const __half2*>(&u1.x));
        float2 b1 = __half22float2(*reinterpret_cast<const __half2*>(&u1.y));
        acc.x += a0.x + b0.x;
        acc.y += a0.y + b0.y;
        acc.z += a1.x + b1.x;
        acc.w += a1.y + b1.y;
    }
    if (e < end) {
        int s0 = g_col[e];
        uint2 u0 = *(const uint2*)(in + (size_t)s0 * HD + lane * 4);
        float2 a0 = __half22float2(*reinterpret_cast<const __half2*>(&u0.x));
        float2 a1 = __half22float2(*reinterpret_cast<const __half2*>(&u0.y));
        acc.x += a0.x;
        acc.y += a0.y;
        acc.z += a1.x;
        acc.w += a1.y;
    }
    float iv = g_inv[warp];
    acc.x *= iv; acc.y *= iv; acc.z *= iv; acc.w *= iv;
    *(float4*)(g_agg + (size_t)warp * HD + lane * 4) = acc;
}

// ---------------- mma.sync helpers ----------------
#define LDSM4(r, addr) \
    asm volatile("ldmatrix.sync.aligned.m8n8.x4.shared.b16 {%0,%1,%2,%3}, [%4];" \
        : "=r"((r)[0]), "=r"((r)[1]), "=r"((r)[2]), "=r"((r)[3]) : "r"(addr))

#define LDSM2(r, addr) \
    asm volatile("ldmatrix.sync.aligned.m8n8.x2.shared.b16 {%0,%1}, [%2];" \
        : "=r"((r)[0]), "=r"((r)[1]) : "r"(addr))

#define MMA16816(d, a, b) \
    asm volatile("mma.sync.aligned.m16n8k16.row.col.f32.bf16.bf16.f32 " \
        "{%0,%1,%2,%3}, {%4,%5,%6,%7}, {%8,%9}, {%0,%1,%2,%3};" \
        : "+f"((d)[0]), "+f"((d)[1]), "+f"((d)[2]), "+f"((d)[3]) \
        : "r"((a)[0]), "r"((a)[1]), "r"((a)[2]), "r"((a)[3]), "r"((b)[0]), "r"((b)[1]))

// swizzled byte offset inside a [rows][128 bf16] plane (256B rows, 16B-chunk XOR)
__device__ __forceinline__ unsigned sw_off(int r, unsigned cbyte) {
    return (unsigned)r * 256u + ((((cbyte >> 4) ^ (unsigned)(r & 7)) & 15u) << 4) + (cbyte & 15u);
}

// stage 128x128 fp32 tile -> split bf16 hi/lo planes (swizzled)
__device__ __forceinline__ void stage_A_sw(char* smhi, char* smlo,
                                           const float* __restrict__ src, int m0, int tid) {
    for (int t = tid; t < 4096; t += 256) {
        int r = t >> 5;
        int c4 = (t & 31) << 2;
        int gr = m0 + r; if (gr > NN - 1) gr = NN - 1;
        float4 v = *(const float4*)(src + (size_t)gr * HD + c4);
        unsigned h01, h23, l01, l23;
        asm("cvt.rn.bf16x2.f32 %0, %1, %2;" : "=r"(h01) : "f"(v.y), "f"(v.x));
        asm("cvt.rn.bf16x2.f32 %0, %1, %2;" : "=r"(h23) : "f"(v.w), "f"(v.z));
        float hx = __uint_as_float(h01 << 16), hy = __uint_as_float(h01 & 0xffff0000u);
        float hz = __uint_as_float(h23 << 16), hw = __uint_as_float(h23 & 0xffff0000u);
        asm("cvt.rn.bf16x2.f32 %0, %1, %2;" : "=r"(l01) : "f"(v.y - hy), "f"(v.x - hx));
        asm("cvt.rn.bf16x2.f32 %0, %1, %2;" : "=r"(l23) : "f"(v.w - hw), "f"(v.z - hz));
        unsigned off = sw_off(r, (unsigned)(c4 * 2));
        *(unsigned long long*)(smhi + off) = (unsigned long long)h01 | ((unsigned long long)h23 << 32);
        *(unsigned long long*)(smlo + off) = (unsigned long long)l01 | ((unsigned long long)l23 << 32);
    }
}

// ---------------- persistent mma GEMM: out = lrelu(agg@Wl + x@Wr + b), Nout=128 ----------------
// smem: A_hi 0, A_lo 32768, B planes 65536 + p*32768 (p: Wl_hi, Wl_lo, Wr_hi, Wr_lo) = 196608
__global__ __launch_bounds__(256, 1) void k_gemm_mma(
    const float* __restrict__ a2ext, int a2_id, int wl_off, int wr_off,
    const float* __restrict__ bias, int out_id)
{
    extern __shared__ char sm[];
    char* Ahi = sm;
    char* Alo = sm + 32768;
    unsigned sAhi = (unsigned)__cvta_generic_to_shared(Ahi);
    unsigned sAlo = (unsigned)__cvta_generic_to_shared(Alo);
    unsigned sB   = (unsigned)__cvta_generic_to_shared(sm + 65536);

    int tid = (int)threadIdx.x;
    int lane = tid & 31, wid = tid >> 5;
    int mwarp = wid & 3, nwarp = wid >> 2;
    const float* a2 = (a2_id < 0) ? a2ext : dev_buf(a2_id);
    float* Out = dev_buf(out_id);

    // stage all four weight planes ONCE
    for (int t = tid; t < 4 * 4096; t += 256) {
        int mtx = t >> 12;
        int e = t & 4095;
        int r = e >> 5, c4 = (e & 31) << 2;
        const unsigned short* wp = ((mtx & 1) ? g_wtl : g_wth) + ((mtx < 2) ? wl_off : wr_off);
        unsigned long long v = *(const unsigned long long*)(wp + r * 128 + c4);
        *(unsigned long long*)(sm + 65536 + mtx * 32768 + sw_off(r, (unsigned)(c4 * 2))) = v;
    }

    int arow0 = mwarp * 32 + (lane & 7) + ((lane >> 3) & 1) * 8;
    unsigned akoff = (unsigned)((lane >> 4) << 4);   // +16B for k+8 half
    int nrow0 = nwarp * 64 + (lane & 7);
    unsigned bkoff = (unsigned)(((lane >> 3) & 1) << 4);

    // hoist bias for this thread's 16 columns
    int r0 = mwarp * 32 + (lane >> 2);
    int cb0 = nwarp * 64 + (lane & 3) * 2;
    float bv0[8], bv1[8];
#pragma unroll
    for (int j = 0; j < 8; j++) { bv0[j] = bias[cb0 + j * 8]; bv1[j] = bias[cb0 + j * 8 + 1]; }

    for (int tile = (int)blockIdx.x; tile < NTILES; tile += (int)gridDim.x) {
        int m0 = tile * 128;

        float acc[2][8][4];
#pragma unroll
        for (int i = 0; i < 2; i++)
#pragma unroll
            for (int j = 0; j < 8; j++)
#pragma unroll
                for (int q = 0; q < 4; q++) acc[i][j][q] = 0.f;

#pragma unroll
        for (int ph = 0; ph < 2; ph++) {
            __syncthreads();   // previous tile's / phase's ldmatrix A reads done; B staged (first pass)
            stage_A_sw(Ahi, Alo, ph ? a2 : g_agg, m0, tid);
            __syncthreads();

            unsigned sBhi = sB + (ph ? 65536u : 0u);
            unsigned sBlo = sBhi + 32768u;

            for (int k0 = 0; k0 < 128; k0 += 16) {
                unsigned ah[2][4], al[2][4], bh[8][2], bl[8][2];
                unsigned acb = (unsigned)(2 * k0) + akoff;
#pragma unroll
                for (int i = 0; i < 2; i++) {
                    int r = arow0 + i * 16;
                    unsigned off = sw_off(r, acb);
                    LDSM4(ah[i], sAhi + off);
                    LDSM4(al[i], sAlo + off);
                }
                unsigned bcb = (unsigned)(2 * k0) + bkoff;
#pragma unroll
                for (int j = 0; j < 8; j++) {
                    int n = nrow0 + j * 8;
                    unsigned off = sw_off(n, bcb);
                    LDSM2(bh[j], sBhi + off);
                    LDSM2(bl[j], sBlo + off);
                }
#pragma unroll
                for (int i = 0; i < 2; i++)
#pragma unroll
                    for (int j = 0; j < 8; j++) {
                        MMA16816(acc[i][j], ah[i], bh[j]);
                        MMA16816(acc[i][j], ah[i], bl[j]);
                        MMA16816(acc[i][j], al[i], bh[j]);
                    }
            }
        }

        // epilogue: bias + leaky relu, fp32 stores + fp16 shadow copy for the next gather
#pragma unroll
        for (int i = 0; i < 2; i++) {
            int rowA = m0 + r0 + i * 16;
            int rowB = rowA + 8;
#pragma unroll
            for (int j = 0; j < 8; j++) {
                int col = cb0 + j * 8;
                float v0 = acc[i][j][0] + bv0[j], v1 = acc[i][j][1] + bv1[j];
                float v2 = acc[i][j][2] + bv0[j], v3 = acc[i][j][3] + bv1[j];
                v0 = (v0 > 0.f) ? v0 : NEG * v0;
                v1 = (v1 > 0.f) ? v1 : NEG * v1;
                v2 = (v2 > 0.f) ? v2 : NEG * v2;
                v3 = (v3 > 0.f) ? v3 : NEG * v3;
                if (rowA < NN) {
                    *(float2*)(Out + (size_t)rowA * HD + col) = make_float2(v0, v1);
                    *(__half2*)(g_h16 + (size_t)rowA * HD + col) = __floats2half2_rn(v0, v1);
                }
                if (rowB < NN) {
                    *(float2*)(Out + (size_t)rowB * HD + col) = make_float2(v2, v3);
                    *(__half2*)(g_h16 + (size_t)rowB * HD + col) = __floats2half2_rn(v2, v3);
                }
            }
        }
    }
}

// ---------------- persistent mma decoder (Nout=40) + fused log_softmax ----------------
// smem: A_hi 0, A_lo 32768, B planes 65536 + p*10240 (total 106496); softmax scratch reuses A
__global__ __launch_bounds__(256, 2) void k_dec_mma(
    int a2_id, int wl_off, int wr_off,
    const float* __restrict__ bias, float* __restrict__ out)
{
    extern __shared__ char sm[];
    char* Ahi = sm;
    char* Alo = sm + 32768;
    unsigned sAhi = (unsigned)__cvta_generic_to_shared(Ahi);
    unsigned sAlo = (unsigned)__cvta_generic_to_shared(Alo);
    unsigned sB   = (unsigned)__cvta_generic_to_shared(sm + 65536);

    int tid = (int)threadIdx.x;
    int lane = tid & 31, wid = tid >> 5;
    const float* a2 = dev_buf(a2_id);

    // stage all four decoder weight planes ONCE (40 rows each)
    for (int t = tid; t < 4 * 1280; t += 256) {
        int mtx = t / 1280;
        int e = t % 1280;
        int r = e >> 5, c4 = (e & 31) << 2;
        const unsigned short* wp = ((mtx & 1) ? g_wtl : g_wth) + ((mtx < 2) ? wl_off : wr_off);
        unsigned long long v = *(const unsigned long long*)(wp + r * 128 + c4);
        *(unsigned long long*)(sm + 65536 + mtx * 10240 + sw_off(r, (unsigned)(c4 * 2))) = v;
    }

    int arow0 = wid * 16 + (lane & 7) + ((lane >> 3) & 1) * 8;
    unsigned akoff = (unsigned)((lane >> 4) << 4);
    int nrow0 = (lane & 7);
    unsigned bkoff = (unsigned)(((lane >> 3) & 1) << 4);

    for (int tile = (int)blockIdx.x; tile < NTILES; tile += (int)gridDim.x) {
        int m0 = tile * 128;

        float acc[5][4];
#pragma unroll
        for (int j = 0; j < 5; j++)
#pragma unroll
            for (int q = 0; q < 4; q++) acc[j][q] = 0.f;

#pragma unroll
        for (int ph = 0; ph < 2; ph++) {
            __syncthreads();   // prior scratch reads / ldmatrix done; B staged (first pass)
            stage_A_sw(Ahi, Alo, ph ? a2 : g_agg, m0, tid);
            __syncthreads();

            unsigned sBhi = sB + (ph ? 20480u : 0u);
            unsigned sBlo = sBhi + 10240u;

            for (int k0 = 0; k0 < 128; k0 += 16) {
                unsigned ah[4], al[4], bh[5][2], bl[5][2];
                unsigned acb = (unsigned)(2 * k0) + akoff;
                unsigned aoff = sw_off(arow0, acb);
                LDSM4(ah, sAhi + aoff);
                LDSM4(al, sAlo + aoff);
                unsigned bcb = (unsigned)(2 * k0) + bkoff;
#pragma unroll
                for (int j = 0; j < 5; j++) {
                    int n = nrow0 + j * 8;
                    unsigned off = sw_off(n, bcb);
                    LDSM2(bh[j], sBhi + off);
                    LDSM2(bl[j], sBlo + off);
                }
#pragma unroll
                for (int j = 0; j < 5; j++) {
                    MMA16816(acc[j], ah, bh[j]);
                    MMA16816(acc[j], ah, bl[j]);
                    MMA16816(acc[j], al, bh[j]);
                }
            }
        }
        __syncthreads();   // all ldmatrix A reads done; reuse A region as scratch

        float* w = (float*)sm + wid * 640;   // 16 rows x 40
        int r0 = lane >> 2, c0 = (lane & 3) * 2;
#pragma unroll
        for (int j = 0; j < 5; j++) {
            int col = j * 8 + c0;
            w[r0 * 40 + col]       = acc[j][0];
            w[r0 * 40 + col + 1]   = acc[j][1];
            w[(r0 + 8) * 40 + col]     = acc[j][2];
            w[(r0 + 8) * 40 + col + 1] = acc[j][3];
        }
        __syncwarp();

        if (lane < 16) {
            float a[40];
#pragma unroll
            for (int c = 0; c < 40; c++) a[c] = w[lane * 40 + c] + bias[c];
            float m = a[0];
#pragma unroll
            for (int c = 1; c < 40; c++) m = fmaxf(m, a[c]);
            float s = 0.f;
#pragma unroll
            for (int c = 0; c < 40; c++) s += __expf(a[c] - m);
            float lse = m + logf(s);
            int row = m0 + wid * 16 + lane;
            if (row < NN) {
#pragma unroll
                for (int j = 0; j < 10; j++) {
                    float4 o;
                    o.x = a[j * 4 + 0] - lse;
                    o.y = a[j * 4 + 1] - lse;
                    o.z = a[j * 4 + 2] - lse;
                    o.w = a[j * 4 + 3] - lse;
                    *(float4*)(out + (size_t)row * CC + j * 4) = o;
                }
            }
        }
        __syncwarp();
    }
}

// ---------------- host ----------------
#define GEMM_SMEM 196608
#define DEC_SMEM  106496
#define NSM 152

extern "C" void kernel_launch(void* const* d_in, const int* in_sizes, int n_in,
                              void* d_out, int out_size) {
    (void)in_sizes; (void)n_in; (void)out_size;
    const float* x      = (const float*)d_in[0];
    const int*   ei     = (const int*)d_in[1];
    const int*   src    = ei;
    const int*   dst    = ei + EE;
    const float* enc_Wl = (const float*)d_in[2];
    const float* enc_Wr = (const float*)d_in[3];
    const float* enc_b  = (const float*)d_in[4];
    const float* lay_Wl = (const float*)d_in[5];
    const float* lay_Wr = (const float*)d_in[6];
    const float* lay_b  = (const float*)d_in[7];
    const float* dec_Wl = (const float*)d_in[8];
    const float* dec_Wr = (const float*)d_in[9];
    const float* dec_b  = (const float*)d_in[10];
    float* out = (float*)d_out;

    cudaFuncSetAttribute(k_gemm_mma, cudaFuncAttributeMaxDynamicSharedMemorySize, GEMM_SMEM);
    cudaFuncSetAttribute(k_dec_mma,  cudaFuncAttributeMaxDynamicSharedMemorySize, DEC_SMEM);

    // merged prep: zero cnt + weight split + x fp16 shadow
    k_prep0<<<(NN * HD / 2 + 255) / 256, 256>>>(x, enc_Wl, enc_Wr, lay_Wl, lay_Wr, dec_Wl, dec_Wr);

    // CSR build
    k_deg<<<(EE + 255) / 256, 256>>>(dst);
    k_scan1<<<(NN + 511) / 512, 512>>>();
    k_scan2<<<1, 128>>>();
    k_prep<<<(NN + 255) / 256, 256>>>();
    k_fill<<<(EE + 255) / 256, 256>>>(src, dst);

    int aggBlocks = (NN + 7) / 8;       // 8 warps / block

    // encoder: h0(bufA) = lrelu(mean(x)@Wl + x@Wr + b)
    k_agg<<<aggBlocks, 256>>>(0);
    k_gemm_mma<<<NSM, 256, GEMM_SMEM>>>(x, -1, WOFF_ENCL, WOFF_ENCR, enc_b, 0);
    // layer 0: bufB
    k_agg<<<aggBlocks, 256>>>(1);
    k_gemm_mma<<<NSM, 256, GEMM_SMEM>>>(nullptr, 0, WOFF_L0L, WOFF_L0R, lay_b, 1);
    // layer 1: bufA
    k_agg<<<aggBlocks, 256>>>(1);
    k_gemm_mma<<<NSM, 256, GEMM_SMEM>>>(nullptr, 1, WOFF_L1L, WOFF_L1R, lay_b + HD, 0);
    // decoder + log_softmax
    k_agg<<<aggBlocks, 256>>>(1);
    k_dec_mma<<<2 * NSM, 256, DEC_SMEM>>>(0, WOFF_DECL, WOFF_DECR, dec_b, out);
}